// round 16
// baseline (speedup 1.0000x reference)
#include <cuda_runtime.h>
#include <cuda_fp16.h>
#include <cstdint>

#define VOCAB 100000
#define BATCH 65536
#define PAIRS (BATCH / 2)
#define NEG 5
#define WPB 8
#define THREADS 256
#define GRID 888                  // 148 SMs * 6 blocks -> one wave at <=42 regs
#define TW (GRID * WPB)           // 7104 warps
#define NV16 (VOCAB * 16)         // uint4 words in fp16 v-table (16B each)

// fp16 copy of v_table: row = 128 halfs = 16 x uint4 (one uint4 per lane).
__device__ uint4 g_v16[NV16];
__device__ float g_partials[GRID];
__device__ unsigned int g_done_count = 0;

// -------------- conversion kernel: v_table f32 -> fp16 (uint4 out) ---------
__global__ __launch_bounds__(256) void convert_v(const float4* __restrict__ v4)
{
    int t = blockIdx.x * 256 + threadIdx.x;
    if (t >= NV16) return;
    float4 f0 = __ldcs(&v4[2 * t]);          // streaming: don't pollute L2
    float4 f1 = __ldcs(&v4[2 * t + 1]);
    __half2 h0 = __floats2half2_rn(f0.x, f0.y);
    __half2 h1 = __floats2half2_rn(f0.z, f0.w);
    __half2 h2 = __floats2half2_rn(f1.x, f1.y);
    __half2 h3 = __floats2half2_rn(f1.z, f1.w);
    uint4 o;
    o.x = *reinterpret_cast<uint32_t*>(&h0);
    o.y = *reinterpret_cast<uint32_t*>(&h1);
    o.z = *reinterpret_cast<uint32_t*>(&h2);
    o.w = *reinterpret_cast<uint32_t*>(&h3);
    g_v16[t] = o;
}

// -------------------------------- main ------------------------------------
__device__ __forceinline__ __half2 u2h2(uint32_t u)
{
    return *reinterpret_cast<__half2*>(&u);
}

// dot of 8 fp16 (uint4) with 8 w-halfs (4 half2), f32 result
__device__ __forceinline__ float dot8(uint4 v, __half2 w0, __half2 w1,
                                      __half2 w2, __half2 w3)
{
    __half2 m = __hmul2(u2h2(v.x), w0);
    m = __hfma2(u2h2(v.y), w1, m);
    m = __hfma2(u2h2(v.z), w2, m);
    m = __hfma2(u2h2(v.w), w3, m);
    return __low2float(m) + __high2float(m);
}

__global__ __launch_bounds__(THREADS, 6) void sgneg_fused(
    const int* __restrict__ pos_w,
    const int* __restrict__ pos_v,
    const int* __restrict__ neg_v,
    const float4* __restrict__ w_table,
    float* __restrict__ out)
{
    const int lane = threadIdx.x & 31;
    const int wib  = threadIdx.x >> 5;
    const int gw   = blockIdx.x * WPB + wib;
    const int half = lane >> 4;         // which element of the pair
    const int hl   = lane & 15;         // lane within half-warp
    const unsigned FULL = 0xFFFFFFFFu;
    const uint4* __restrict__ v16 = g_v16;

    float acc = 0.0f;

    for (int pr = gw; pr < PAIRS; pr += TW) {
        const int e = 2 * pr + half;    // this half-warp's element

        // Indices (uniform per half-warp):
        //   w_table in float4 units (<<5), v16 in uint4 units (<<4)
        const int wi  = pos_w[e] << 5;
        const int pvi = pos_v[e] << 4;
        const int ni0 = neg_v[e * NEG + 0] << 4;
        const int ni1 = neg_v[e * NEG + 1] << 4;
        const int ni2 = neg_v[e * NEG + 2] << 4;
        const int ni3 = neg_v[e * NEG + 3] << 4;
        const int ni4 = neg_v[e * NEG + 4] << 4;

        // w: 8 floats/lane (2 float4); v rows: 8 fp16/lane (1 uint4, 256B/half)
        const float4 wa = w_table[wi + 2 * hl];
        const float4 wb = w_table[wi + 2 * hl + 1];
        const uint4  p  = v16[pvi + hl];
        const uint4  n0 = v16[ni0 + hl];
        const uint4  n1 = v16[ni1 + hl];
        const uint4  n2 = v16[ni2 + hl];
        const uint4  n3 = v16[ni3 + hl];
        const uint4  n4 = v16[ni4 + hl];

        const __half2 w0 = __floats2half2_rn(wa.x, wa.y);
        const __half2 w1 = __floats2half2_rn(wa.z, wa.w);
        const __half2 w2 = __floats2half2_rn(wb.x, wb.y);
        const __half2 w3 = __floats2half2_rn(wb.z, wb.w);

        float d0 = dot8(p,  w0, w1, w2, w3);
        float d1 = dot8(n0, w0, w1, w2, w3);
        float d2 = dot8(n1, w0, w1, w2, w3);
        float d3 = dot8(n2, w0, w1, w2, w3);
        float d4 = dot8(n3, w0, w1, w2, w3);
        float d5 = dot8(n4, w0, w1, w2, w3);

        // Packed 6-value reduction within each 16-lane half: 12 shuffles
        // (offsets 8,4,2,1 never cross the half boundary).
        float t, u;
        t = __shfl_xor_sync(FULL, d0, 8);
        u = __shfl_xor_sync(FULL, d1, 8);
        float e0 = (hl & 8) ? d1 + u : d0 + t;
        t = __shfl_xor_sync(FULL, d2, 8);
        u = __shfl_xor_sync(FULL, d3, 8);
        float e1 = (hl & 8) ? d3 + u : d2 + t;
        t = __shfl_xor_sync(FULL, d4, 8);
        u = __shfl_xor_sync(FULL, d5, 8);
        float e2 = (hl & 8) ? d5 + u : d4 + t;
        t = __shfl_xor_sync(FULL, e0, 4);
        u = __shfl_xor_sync(FULL, e1, 4);
        float f0 = (hl & 4) ? e1 + u : e0 + t;
        e2 += __shfl_xor_sync(FULL, e2, 4);
        t = __shfl_xor_sync(FULL, f0, 2);
        u = __shfl_xor_sync(FULL, e2, 2);
        float g = (hl & 2) ? e2 + u : f0 + t;
        g += __shfl_xor_sync(FULL, g, 1);

        // Owner lanes per half: hl in {0,8,4,12,2,10}; hl==0 is the positive
        const bool active = ((hl & 1) == 0) && !((hl & 2) && (hl & 4));
        float x = fminf(fmaxf(g, -10.0f), 10.0f);
        if (hl != 0) x = -x;
        float term = -__logf(1.0f + __expf(-x));   // log_sigmoid, x in [-10,10]
        acc += active ? term : 0.0f;
    }

    // End-of-kernel full-warp reduction of acc
#pragma unroll
    for (int off = 16; off > 0; off >>= 1)
        acc += __shfl_xor_sync(FULL, acc, off);

    __shared__ float sh[WPB];
    if (lane == 0) sh[wib] = acc;
    __syncthreads();

    __shared__ bool is_last;
    if (threadIdx.x == 0) {
        float s = 0.0f;
#pragma unroll
        for (int i = 0; i < WPB; i++) s += sh[i];
        g_partials[blockIdx.x] = s;
        __threadfence();
        unsigned int old = atomicAdd(&g_done_count, 1u);
        is_last = (old == (unsigned int)(GRID - 1));
    }
    __syncthreads();

    if (is_last) {
        __shared__ double shd[THREADS];
        double s = 0.0;
        for (int i = threadIdx.x; i < GRID; i += THREADS)
            s += (double)g_partials[i];
        shd[threadIdx.x] = s;
        __syncthreads();
#pragma unroll
        for (int st = THREADS / 2; st > 0; st >>= 1) {
            if (threadIdx.x < st) shd[threadIdx.x] += shd[threadIdx.x + st];
            __syncthreads();
        }
        if (threadIdx.x == 0) {
            out[0] = (float)(-shd[0]);
            g_done_count = 0;   // reset for next graph replay
        }
    }
}

extern "C" void kernel_launch(void* const* d_in, const int* in_sizes, int n_in,
                              void* d_out, int out_size)
{
    const int*    pos_w   = (const int*)d_in[0];
    const int*    pos_v   = (const int*)d_in[1];
    const int*    neg_v   = (const int*)d_in[2];
    const float4* w_table = (const float4*)d_in[3];
    const float4* v_table = (const float4*)d_in[4];
    float*        out     = (float*)d_out;

    convert_v<<<(NV16 + 255) / 256, 256>>>(v_table);
    sgneg_fused<<<GRID, THREADS>>>(pos_w, pos_v, neg_v, w_table, out);
}

// round 17
// speedup vs baseline: 1.1861x; 1.1861x over previous
#include <cuda_runtime.h>
#include <cuda_fp8.h>
#include <cuda_fp16.h>
#include <cstdint>

#define VOCAB 100000
#define BATCH 65536
#define QUADS (BATCH / 4)
#define NEG 5
#define WPB 8
#define THREADS 256
#define GRID 740                  // 148 SMs * 5 blocks -> one wave at <=51 regs
#define TW (GRID * WPB)           // 5920 warps
#define NVQ (VOCAB * 8)           // uint4 words in fp8 v-table (16B each)

#define VSCALE 64.0f
#define INV_VSCALE 0.015625f

// fp8(e4m3) copy of v_table, scaled by 64. Row = 128 fp8 = 8 x uint4.
__device__ uint4 g_v8[NVQ];
__device__ float g_partials[GRID];
__device__ unsigned int g_done_count = 0;

// -------------- conversion kernel: v_table f32 -> fp8*64 (uint4 out) -------
__global__ __launch_bounds__(256) void convert_v(const float4* __restrict__ v4)
{
    int t = blockIdx.x * 256 + threadIdx.x;
    if (t >= NVQ) return;
    float4 f0 = __ldcs(&v4[4 * t]);          // streaming: don't pollute L2
    float4 f1 = __ldcs(&v4[4 * t + 1]);
    float4 f2 = __ldcs(&v4[4 * t + 2]);
    float4 f3 = __ldcs(&v4[4 * t + 3]);
    uint32_t a0 = __nv_cvt_float2_to_fp8x2(make_float2(f0.x * VSCALE, f0.y * VSCALE), __NV_SATFINITE, __NV_E4M3);
    uint32_t a1 = __nv_cvt_float2_to_fp8x2(make_float2(f0.z * VSCALE, f0.w * VSCALE), __NV_SATFINITE, __NV_E4M3);
    uint32_t b0 = __nv_cvt_float2_to_fp8x2(make_float2(f1.x * VSCALE, f1.y * VSCALE), __NV_SATFINITE, __NV_E4M3);
    uint32_t b1 = __nv_cvt_float2_to_fp8x2(make_float2(f1.z * VSCALE, f1.w * VSCALE), __NV_SATFINITE, __NV_E4M3);
    uint32_t c0 = __nv_cvt_float2_to_fp8x2(make_float2(f2.x * VSCALE, f2.y * VSCALE), __NV_SATFINITE, __NV_E4M3);
    uint32_t c1 = __nv_cvt_float2_to_fp8x2(make_float2(f2.z * VSCALE, f2.w * VSCALE), __NV_SATFINITE, __NV_E4M3);
    uint32_t d0 = __nv_cvt_float2_to_fp8x2(make_float2(f3.x * VSCALE, f3.y * VSCALE), __NV_SATFINITE, __NV_E4M3);
    uint32_t d1 = __nv_cvt_float2_to_fp8x2(make_float2(f3.z * VSCALE, f3.w * VSCALE), __NV_SATFINITE, __NV_E4M3);
    uint4 o;
    o.x = a0 | (a1 << 16);
    o.y = b0 | (b1 << 16);
    o.z = c0 | (c1 << 16);
    o.w = d0 | (d1 << 16);
    g_v8[t] = o;
}

// -------------------------------- main ------------------------------------
__device__ __forceinline__ __half2 raw2h2(__half2_raw r)
{
    __half2 h;
    *reinterpret_cast<__half2_raw*>(&h) = r;
    return h;
}

__device__ __forceinline__ __half2 fp8lo(uint32_t u)
{
    return raw2h2(__nv_cvt_fp8x2_to_halfraw2((__nv_fp8x2_storage_t)(u & 0xFFFFu), __NV_E4M3));
}
__device__ __forceinline__ __half2 fp8hi(uint32_t u)
{
    return raw2h2(__nv_cvt_fp8x2_to_halfraw2((__nv_fp8x2_storage_t)(u >> 16), __NV_E4M3));
}

// dot of 16 fp8 (uint4) with 16 w-halfs (8 half2), f32 result
__device__ __forceinline__ float dot16(uint4 v, const __half2 w[8])
{
    __half2 m = __hmul2(fp8lo(v.x), w[0]);
    m = __hfma2(fp8hi(v.x), w[1], m);
    m = __hfma2(fp8lo(v.y), w[2], m);
    m = __hfma2(fp8hi(v.y), w[3], m);
    m = __hfma2(fp8lo(v.z), w[4], m);
    m = __hfma2(fp8hi(v.z), w[5], m);
    m = __hfma2(fp8lo(v.w), w[6], m);
    m = __hfma2(fp8hi(v.w), w[7], m);
    return __low2float(m) + __high2float(m);
}

__global__ __launch_bounds__(THREADS, 5) void sgneg_fused(
    const int* __restrict__ pos_w,
    const int* __restrict__ pos_v,
    const int* __restrict__ neg_v,
    const float4* __restrict__ w_table,
    float* __restrict__ out)
{
    const int lane = threadIdx.x & 31;
    const int wib  = threadIdx.x >> 5;
    const int gw   = blockIdx.x * WPB + wib;
    const int q    = lane >> 3;          // which element of the quad (0..3)
    const int ql   = lane & 7;           // lane within 8-lane group
    const unsigned FULL = 0xFFFFFFFFu;
    const uint4* __restrict__ v8 = g_v8;

    float acc = 0.0f;

    for (int pr = gw; pr < QUADS; pr += TW) {
        const int e = 4 * pr + q;        // this group's element

        // Indices (uniform per 8-lane group):
        //   w_table in float4 units (<<5), v8 in uint4 units (<<3)
        const int wi  = pos_w[e] << 5;
        const int pvi = pos_v[e] << 3;
        const int ni0 = neg_v[e * NEG + 0] << 3;
        const int ni1 = neg_v[e * NEG + 1] << 3;
        const int ni2 = neg_v[e * NEG + 2] << 3;
        const int ni3 = neg_v[e * NEG + 3] << 3;
        const int ni4 = neg_v[e * NEG + 4] << 3;

        // w: 16 floats/lane (4 float4, dims 16*ql..16*ql+15), cvt to 8 half2
        __half2 w[8];
        {
            const float4 wa = w_table[wi + 4 * ql + 0];
            const float4 wb = w_table[wi + 4 * ql + 1];
            const float4 wc = w_table[wi + 4 * ql + 2];
            const float4 wd = w_table[wi + 4 * ql + 3];
            w[0] = __floats2half2_rn(wa.x, wa.y);
            w[1] = __floats2half2_rn(wa.z, wa.w);
            w[2] = __floats2half2_rn(wb.x, wb.y);
            w[3] = __floats2half2_rn(wb.z, wb.w);
            w[4] = __floats2half2_rn(wc.x, wc.y);
            w[5] = __floats2half2_rn(wc.z, wc.w);
            w[6] = __floats2half2_rn(wd.x, wd.y);
            w[7] = __floats2half2_rn(wd.z, wd.w);
        }

        // v rows: 16 fp8/lane (1 uint4, one LDG.128 per row per warp)
        const uint4 p  = v8[pvi + ql];
        const uint4 n0 = v8[ni0 + ql];
        const uint4 n1 = v8[ni1 + ql];
        const uint4 n2 = v8[ni2 + ql];
        const uint4 n3 = v8[ni3 + ql];
        const uint4 n4 = v8[ni4 + ql];

        float d0 = dot16(p,  w);
        float d1 = dot16(n0, w);
        float d2 = dot16(n1, w);
        float d3 = dot16(n2, w);
        float d4 = dot16(n3, w);
        float d5 = dot16(n4, w);

        // Packed 6-value reduction within each 8-lane group: 11 shuffles
        // (offsets 4,2,1 never cross the group boundary).
        float t, u;
        t = __shfl_xor_sync(FULL, d0, 4);
        u = __shfl_xor_sync(FULL, d1, 4);
        float e0 = (ql & 4) ? d1 + u : d0 + t;
        t = __shfl_xor_sync(FULL, d2, 4);
        u = __shfl_xor_sync(FULL, d3, 4);
        float e1 = (ql & 4) ? d3 + u : d2 + t;
        t = __shfl_xor_sync(FULL, d4, 4);
        u = __shfl_xor_sync(FULL, d5, 4);
        float e2 = (ql & 4) ? d5 + u : d4 + t;
        t = __shfl_xor_sync(FULL, e0, 2);
        u = __shfl_xor_sync(FULL, e1, 2);
        float f0 = (ql & 2) ? e1 + u : e0 + t;
        e2 += __shfl_xor_sync(FULL, e2, 2);
        t = __shfl_xor_sync(FULL, f0, 1);
        u = __shfl_xor_sync(FULL, e2, 1);
        float g = (ql & 1) ? e2 + u : f0 + t;

        // Owner lanes per group: ql 0->d0(pos), 4->d1, 2->d2, 6->d3, 1->d4, 5->d5
        // ql 3,7 are duplicates -> masked out.
        const bool active = (!(ql & 1)) || (!(ql & 2));
        g *= INV_VSCALE;                      // undo fp8 pre-scale
        float x = fminf(fmaxf(g, -10.0f), 10.0f);
        if (ql != 0) x = -x;
        float term = -__logf(1.0f + __expf(-x));   // log_sigmoid, x in [-10,10]
        acc += active ? term : 0.0f;
    }

    // End-of-kernel full-warp reduction of acc
#pragma unroll
    for (int off = 16; off > 0; off >>= 1)
        acc += __shfl_xor_sync(FULL, acc, off);

    __shared__ float sh[WPB];
    if (lane == 0) sh[wib] = acc;
    __syncthreads();

    __shared__ bool is_last;
    if (threadIdx.x == 0) {
        float s = 0.0f;
#pragma unroll
        for (int i = 0; i < WPB; i++) s += sh[i];
        g_partials[blockIdx.x] = s;
        __threadfence();
        unsigned int old = atomicAdd(&g_done_count, 1u);
        is_last = (old == (unsigned int)(GRID - 1));
    }
    __syncthreads();

    if (is_last) {
        __shared__ double shd[THREADS];
        double s = 0.0;
        for (int i = threadIdx.x; i < GRID; i += THREADS)
            s += (double)g_partials[i];
        shd[threadIdx.x] = s;
        __syncthreads();
#pragma unroll
        for (int st = THREADS / 2; st > 0; st >>= 1) {
            if (threadIdx.x < st) shd[threadIdx.x] += shd[threadIdx.x + st];
            __syncthreads();
        }
        if (threadIdx.x == 0) {
            out[0] = (float)(-shd[0]);
            g_done_count = 0;   // reset for next graph replay
        }
    }
}

extern "C" void kernel_launch(void* const* d_in, const int* in_sizes, int n_in,
                              void* d_out, int out_size)
{
    const int*    pos_w   = (const int*)d_in[0];
    const int*    pos_v   = (const int*)d_in[1];
    const int*    neg_v   = (const int*)d_in[2];
    const float4* w_table = (const float4*)d_in[3];
    const float4* v_table = (const float4*)d_in[4];
    float*        out     = (float*)d_out;

    convert_v<<<(NVQ + 255) / 256, 256>>>(v_table);
    sgneg_fused<<<GRID, THREADS>>>(pos_w, pos_v, neg_v, w_table, out);
}